// round 3
// baseline (speedup 1.0000x reference)
#include <cuda_runtime.h>

// Fused coefficients: [ka0, kc0, ka1, kc1, bias]
__device__ float g_coef[5];

#define LAYERS 8
#define N_QUBITS 16

// Thread q (q=0,1) composes the 8-layer Rot chain for qubit q into one 2x2
// complex unitary, reduces it to the (A, C) pair of the closed form
//   ez(x) = A*cos(x) - C*sin(x),
// and folds in the linear head.
__global__ void vqc_precompute_kernel(const float* __restrict__ params,
                                      const float* __restrict__ head_w,
                                      const float* __restrict__ head_b) {
    int q = threadIdx.x;
    if (q >= 2) return;

    float u00r = 1.f, u00i = 0.f, u01r = 0.f, u01i = 0.f;
    float u10r = 0.f, u10i = 0.f, u11r = 1.f, u11i = 0.f;

    #pragma unroll
    for (int l = 0; l < LAYERS; l++) {
        float phi   = params[l * (N_QUBITS * 3) + q * 3 + 0];
        float theta = params[l * (N_QUBITS * 3) + q * 3 + 1];
        float omega = params[l * (N_QUBITS * 3) + q * 3 + 2];
        float ct, st, cp, sp, cm, sm;
        __sincosf(0.5f * theta, &st, &ct);
        __sincosf(-0.5f * (phi + omega), &sp, &cp);
        __sincosf(0.5f * (phi - omega), &sm, &cm);
        // Rot(phi,theta,omega) = RZ(omega) RY(theta) RZ(phi)
        float m00r =  cp * ct, m00i =  sp * ct;
        float m01r = -cm * st, m01i = -sm * st;
        float m10r =  cm * st, m10i = -sm * st;
        float m11r =  cp * ct, m11i = -sp * ct;

        float n00r = m00r*u00r - m00i*u00i + m01r*u10r - m01i*u10i;
        float n00i = m00r*u00i + m00i*u00r + m01r*u10i + m01i*u10r;
        float n01r = m00r*u01r - m00i*u01i + m01r*u11r - m01i*u11i;
        float n01i = m00r*u01i + m00i*u01r + m01r*u11i + m01i*u11r;
        float n10r = m10r*u00r - m10i*u00i + m11r*u10r - m11i*u10i;
        float n10i = m10r*u00i + m10i*u00r + m11r*u10i + m11i*u10r;
        float n11r = m10r*u01r - m10i*u01i + m11r*u11r - m11i*u11i;
        float n11i = m10r*u01i + m10i*u01r + m11r*u11i + m11i*u11r;
        u00r = n00r; u00i = n00i; u01r = n01r; u01i = n01i;
        u10r = n10r; u10i = n10i; u11r = n11r; u11i = n11i;
    }

    float A = (u00r*u00r + u00i*u00i) - (u10r*u10r + u10i*u10i);
    float C = (u00i*u01r - u00r*u01i) - (u10i*u11r - u10r*u11i);

    float w = head_w[q];
    g_coef[q * 2 + 0] = w * A;
    g_coef[q * 2 + 1] = w * C;
    if (q == 0) g_coef[4] = head_b[0];
}

// Dense-stream kernel: 4 threads per batch row. Every thread issues one
// coalesced float4 load (warp = 512 contiguous bytes, 100% sector density so
// HBM streams at full row-buffer efficiency). Only the lane holding the first
// 16 bytes of a row (tid%4==0, which has x0,x1 in .x,.y) computes and stores.
__global__ void __launch_bounds__(256)
vqc_main_kernel(const float4* __restrict__ X4, float* __restrict__ out, int n4) {
    int t = blockIdx.x * blockDim.x + threadIdx.x;
    if (t >= n4) return;

    float4 v = __ldg(X4 + t);

    if ((t & 3) == 0) {
        float ka0 = g_coef[0], kc0 = g_coef[1];
        float ka1 = g_coef[2], kc1 = g_coef[3];
        float bias = g_coef[4];

        float s0, c0, s1, c1;
        __sincosf(v.x, &s0, &c0);
        __sincosf(v.y, &s1, &c1);

        out[t >> 2] = fmaf(ka0, c0, fmaf(-kc0, s0,
                      fmaf(ka1, c1, fmaf(-kc1, s1, bias))));
    }
}

extern "C" void kernel_launch(void* const* d_in, const int* in_sizes, int n_in,
                              void* d_out, int out_size) {
    const float* X      = (const float*)d_in[0];   // [B, 16]
    const float* params = (const float*)d_in[1];   // [8, 16, 3]
    const float* head_w = (const float*)d_in[2];   // [1, 2]
    const float* head_b = (const float*)d_in[3];   // [1]
    float* out = (float*)d_out;

    int B = in_sizes[0] / N_QUBITS;
    int n4 = B * 4;  // one float4 per thread, 4 threads per row

    vqc_precompute_kernel<<<1, 32>>>(params, head_w, head_b);
    vqc_main_kernel<<<(n4 + 255) / 256, 256>>>((const float4*)X, out, n4);
}

// round 4
// speedup vs baseline: 1.4926x; 1.4926x over previous
#include <cuda_runtime.h>

// Fused coefficients: [ka0, kc0, ka1, kc1, bias]
__device__ float g_coef[5];

#define LAYERS 8
#define N_QUBITS 16
#define ROWS_PER_THREAD 8

// Thread q (q=0,1) composes the 8-layer Rot chain for qubit q into one 2x2
// complex unitary, reduces it to the (A, C) pair of the closed form
//   ez(x) = A*cos(x) - C*sin(x),  and folds in the linear head.
__global__ void vqc_precompute_kernel(const float* __restrict__ params,
                                      const float* __restrict__ head_w,
                                      const float* __restrict__ head_b) {
    int q = threadIdx.x;
    if (q >= 2) return;

    float u00r = 1.f, u00i = 0.f, u01r = 0.f, u01i = 0.f;
    float u10r = 0.f, u10i = 0.f, u11r = 1.f, u11i = 0.f;

    #pragma unroll
    for (int l = 0; l < LAYERS; l++) {
        float phi   = params[l * (N_QUBITS * 3) + q * 3 + 0];
        float theta = params[l * (N_QUBITS * 3) + q * 3 + 1];
        float omega = params[l * (N_QUBITS * 3) + q * 3 + 2];
        float ct, st, cp, sp, cm, sm;
        __sincosf(0.5f * theta, &st, &ct);
        __sincosf(-0.5f * (phi + omega), &sp, &cp);
        __sincosf(0.5f * (phi - omega), &sm, &cm);
        float m00r =  cp * ct, m00i =  sp * ct;
        float m01r = -cm * st, m01i = -sm * st;
        float m10r =  cm * st, m10i = -sm * st;
        float m11r =  cp * ct, m11i = -sp * ct;

        float n00r = m00r*u00r - m00i*u00i + m01r*u10r - m01i*u10i;
        float n00i = m00r*u00i + m00i*u00r + m01r*u10i + m01i*u10r;
        float n01r = m00r*u01r - m00i*u01i + m01r*u11r - m01i*u11i;
        float n01i = m00r*u01i + m00i*u01r + m01r*u11i + m01i*u11r;
        float n10r = m10r*u00r - m10i*u00i + m11r*u10r - m11i*u10i;
        float n10i = m10r*u00i + m10i*u00r + m11r*u10i + m11i*u10r;
        float n11r = m10r*u01r - m10i*u01i + m11r*u11r - m11i*u11i;
        float n11i = m10r*u01i + m10i*u01r + m11r*u11i + m11i*u11r;
        u00r = n00r; u00i = n00i; u01r = n01r; u01i = n01i;
        u10r = n10r; u10i = n10i; u11r = n11r; u11i = n11i;
    }

    float A = (u00r*u00r + u00i*u00i) - (u10r*u10r + u10i*u10i);
    float C = (u00i*u01r - u00r*u01i) - (u10i*u11r - u10r*u11i);

    float w = head_w[q];
    g_coef[q * 2 + 0] = w * A;
    g_coef[q * 2 + 1] = w * C;
    if (q == 0) g_coef[4] = head_b[0];
}

// MLP-deep streaming kernel: each thread handles ROWS_PER_THREAD rows, issuing
// all 8-byte row-prefix loads up front (8 independent LDG.64 in flight per
// thread) before computing. Loads and stores are coalesced per iteration
// (row index = tid + i*nthreads).
__global__ void __launch_bounds__(256)
vqc_main_kernel(const float* __restrict__ X, float* __restrict__ out, int B) {
    int tid = blockIdx.x * blockDim.x + threadIdx.x;
    int nthreads = gridDim.x * blockDim.x;

    float ka0 = g_coef[0], kc0 = g_coef[1];
    float ka1 = g_coef[2], kc1 = g_coef[3];
    float bias = g_coef[4];

    float x0[ROWS_PER_THREAD], x1[ROWS_PER_THREAD];

    #pragma unroll
    for (int i = 0; i < ROWS_PER_THREAD; i++) {
        int b = tid + i * nthreads;
        if (b < B) {
            const float* p = X + (size_t)b * N_QUBITS;
            asm volatile("ld.global.nc.v2.f32 {%0, %1}, [%2];"
                         : "=f"(x0[i]), "=f"(x1[i]) : "l"(p));
        }
    }

    #pragma unroll
    for (int i = 0; i < ROWS_PER_THREAD; i++) {
        int b = tid + i * nthreads;
        if (b < B) {
            float s0, c0, s1, c1;
            __sincosf(x0[i], &s0, &c0);
            __sincosf(x1[i], &s1, &c1);
            out[b] = fmaf(ka0, c0, fmaf(-kc0, s0,
                     fmaf(ka1, c1, fmaf(-kc1, s1, bias))));
        }
    }
}

extern "C" void kernel_launch(void* const* d_in, const int* in_sizes, int n_in,
                              void* d_out, int out_size) {
    const float* X      = (const float*)d_in[0];   // [B, 16]
    const float* params = (const float*)d_in[1];   // [8, 16, 3]
    const float* head_w = (const float*)d_in[2];   // [1, 2]
    const float* head_b = (const float*)d_in[3];   // [1]
    float* out = (float*)d_out;

    int B = in_sizes[0] / N_QUBITS;

    int threads = 256;
    int total_threads = (B + ROWS_PER_THREAD - 1) / ROWS_PER_THREAD;
    int blocks = (total_threads + threads - 1) / threads;

    vqc_precompute_kernel<<<1, 32>>>(params, head_w, head_b);
    vqc_main_kernel<<<blocks, threads>>>(X, out, B);
}